// round 10
// baseline (speedup 1.0000x reference)
#include <cuda_runtime.h>
#include <cuda_bf16.h>
#include <math.h>

// ---------------- problem constants ----------------
#define R_NUM 5
#define N1T   30000
#define N2T   15000
#define IN_DIM 128
#define HC0   256
#define H0    4
#define C0    64
#define HC1   40
#define C1    40
#define E0MAX 300000
#define E1MAX 150000

// ---------------- scratch ----------------
__device__ __nv_bfloat16 g_xbf [(size_t)N1T * IN_DIM];
__device__ float g_hj0 [(size_t)N1T * HC0];
__device__ float g_h0all[(size_t)N2T * 512];              // [hi0 | x1self+bias]
__device__ float g_den0[(size_t)N2T * R_NUM * H0];
__device__ __nv_bfloat16 g_z0bf[(size_t)R_NUM * N2T * HC0];
__device__ __nv_bfloat16 g_qkv0bf[(size_t)3 * R_NUM * N2T * HC0]; // q|k|v
__device__ __nv_bfloat16 g_x1bf[(size_t)N2T * HC0];
__device__ float g_h1all[(size_t)N2T * 120];              // [hj1 | hi1 | o1self+bias]
__device__ float g_den1[(size_t)N2T * R_NUM];
__device__ __nv_bfloat16 g_z1bf[(size_t)R_NUM * N2T * HC1];
__device__ __nv_bfloat16 g_z1p [(size_t)R_NUM * N2T * 64];
__device__ float g_qkv1[(size_t)R_NUM * N2T * 120];
// weights (transposed / packed, bf16)
__device__ __nv_bfloat16 g_wj0t  [(size_t)HC0 * IN_DIM];
__device__ __nv_bfloat16 g_w0pack[(size_t)512 * IN_DIM];
__device__ float         g_b0pack[512];
__device__ __nv_bfloat16 g_wqkv0t[(size_t)3 * R_NUM * HC0 * HC0];
__device__ __nv_bfloat16 g_w1pack[(size_t)120 * HC0];
__device__ float         g_b1pack[120];
__device__ __nv_bfloat16 g_wqkv1t[(size_t)R_NUM * 120 * 64];

static inline int cdiv(int a, int b) { return (a + b - 1) / b; }

// ---------------- cp.async helpers ----------------
__device__ __forceinline__ void cp16(void* dst, const void* src, bool ok) {
    unsigned d = (unsigned)__cvta_generic_to_shared(dst);
    int n = ok ? 16 : 0;
    asm volatile("cp.async.cg.shared.global [%0], [%1], 16, %2;\n"
                 :: "r"(d), "l"(src), "r"(n));
}
__device__ __forceinline__ void cp_commit() {
    asm volatile("cp.async.commit_group;\n");
}
template <int N> __device__ __forceinline__ void cp_wait() {
    asm volatile("cp.async.wait_group %0;\n" :: "n"(N));
}

// ---------------- tensor-core primitives ----------------
__device__ __forceinline__ void mma16816(float* d, const unsigned* a,
                                         const unsigned* b0, const unsigned* b1,
                                         const float* c)
{
    asm volatile(
        "mma.sync.aligned.m16n8k16.row.col.f32.bf16.bf16.f32 "
        "{%0,%1,%2,%3}, {%4,%5,%6,%7}, {%8,%9}, {%10,%11,%12,%13};\n"
        : "=f"(d[0]), "=f"(d[1]), "=f"(d[2]), "=f"(d[3])
        : "r"(a[0]), "r"(a[1]), "r"(a[2]), "r"(a[3]),
          "r"(*b0), "r"(*b1),
          "f"(c[0]), "f"(c[1]), "f"(c[2]), "f"(c[3]));
}

__device__ __forceinline__ void ldsm4(unsigned* r, unsigned addr)
{
    asm volatile("ldmatrix.sync.aligned.m8n8.x4.shared.b16 {%0,%1,%2,%3}, [%4];"
                 : "=r"(r[0]), "=r"(r[1]), "=r"(r[2]), "=r"(r[3]) : "r"(addr));
}

// vector reduction: 4x bf16x2 (16 bytes) in one red op
__device__ __forceinline__ void red_v4_bf16x2(void* addr, unsigned p0, unsigned p1,
                                              unsigned p2, unsigned p3)
{
    asm volatile("red.global.add.noftz.v4.bf16x2 [%0], {%1,%2,%3,%4};"
                 :: "l"(addr), "r"(p0), "r"(p1), "r"(p2), "r"(p3) : "memory");
}

#define TBM 128
#define TBN 128
#define TLD 40

// C[M,N] = A[M,K](bf16 rm) @ Bt[N,K](bf16) (+bias). 3-stage cp.async + ldmatrix.
template <typename OT>
__device__ __forceinline__ void gemm_tc_body(const __nv_bfloat16* __restrict__ A,
                                             const __nv_bfloat16* __restrict__ Bt,
                                             const float* __restrict__ bias,
                                             OT* __restrict__ C,
                                             int M, int N, int K)
{
    __shared__ __nv_bfloat16 As[3][TBM * TLD];
    __shared__ __nv_bfloat16 Bs[3][TBN * TLD];
    int tid = threadIdx.x;
    int wid = tid >> 5, lane = tid & 31;
    int wm = wid >> 1, wn = wid & 1;
    int m0 = blockIdx.y * TBM, n0 = blockIdx.x * TBN;
    int g = lane >> 2, cq = lane & 3;
    int r0 = tid >> 2, kg = (tid & 3) * 8;

    float acc[2][8][4];
#pragma unroll
    for (int i = 0; i < 2; i++)
#pragma unroll
        for (int j = 0; j < 8; j++)
#pragma unroll
            for (int q = 0; q < 4; q++) acc[i][j][q] = 0.f;

    int nt = K >> 5;

    auto load_stage = [&](int s, int kt, bool active) {
        if (active) {
#pragma unroll
            for (int it = 0; it < 2; it++) {
                int r = r0 + it * 64;
                bool okA = (m0 + r) < M;
                bool okB = (n0 + r) < N;
                const __nv_bfloat16* pa = A + (size_t)(okA ? (m0 + r) : 0) * K + kt + kg;
                const __nv_bfloat16* pb = Bt + (size_t)(okB ? (n0 + r) : 0) * K + kt + kg;
                cp16(&As[s][r * TLD + kg], pa, okA);
                cp16(&Bs[s][r * TLD + kg], pb, okB);
            }
        }
        cp_commit();
    };

    // ldmatrix source offsets (elements within a stage)
    int aoff[2], boff[4];
#pragma unroll
    for (int mf = 0; mf < 2; mf++)
        aoff[mf] = (wm * 32 + mf * 16 + (lane & 15)) * TLD + ((lane >> 4) << 3);
#pragma unroll
    for (int p = 0; p < 4; p++)
        boff[p] = (wn * 64 + p * 16 + ((lane >> 4) << 3) + (lane & 7)) * TLD
                  + (((lane >> 3) & 1) << 3);

    unsigned asb[3], bsb[3];
#pragma unroll
    for (int s = 0; s < 3; s++) {
        asb[s] = (unsigned)__cvta_generic_to_shared(&As[s][0]);
        bsb[s] = (unsigned)__cvta_generic_to_shared(&Bs[s][0]);
    }

    load_stage(0, 0, true);
    load_stage(1, 32, nt > 1);

    for (int i = 0; i < nt; i++) {
        load_stage((i + 2) % 3, (i + 2) << 5, (i + 2) < nt);
        cp_wait<2>();
        __syncthreads();
        int s = i % 3;
#pragma unroll
        for (int ks = 0; ks < 2; ks++) {
            int kb = ks * 16;
            unsigned a[2][4], b[4][4];
#pragma unroll
            for (int mf = 0; mf < 2; mf++)
                ldsm4(a[mf], asb[s] + (unsigned)(aoff[mf] + kb) * 2);
#pragma unroll
            for (int p = 0; p < 4; p++)
                ldsm4(b[p], bsb[s] + (unsigned)(boff[p] + kb) * 2);
#pragma unroll
            for (int mf = 0; mf < 2; mf++)
#pragma unroll
                for (int nf = 0; nf < 8; nf++)
                    mma16816(acc[mf][nf], a[mf],
                             &b[nf >> 1][(nf & 1) * 2], &b[nf >> 1][(nf & 1) * 2 + 1],
                             acc[mf][nf]);
        }
        __syncthreads();
    }

#pragma unroll
    for (int mf = 0; mf < 2; mf++) {
#pragma unroll
        for (int nf = 0; nf < 8; nf++) {
            int col = n0 + wn * 64 + nf * 8 + cq * 2;
            int row = m0 + wm * 32 + mf * 16 + g;
            if (col >= N) continue;
            float b0 = 0.f, b1 = 0.f;
            if (bias) { b0 = bias[col]; b1 = bias[col + 1]; }
#pragma unroll
            for (int half = 0; half < 2; half++) {
                int rr = row + half * 8;
                if (rr >= M) continue;
                float x0 = acc[mf][nf][half * 2 + 0] + b0;
                float x1 = acc[mf][nf][half * 2 + 1] + b1;
                if constexpr (sizeof(OT) == 2) {
                    __nv_bfloat162 v = __floats2bfloat162_rn(x0, x1);
                    *reinterpret_cast<__nv_bfloat162*>(
                        (__nv_bfloat16*)C + (size_t)rr * N + col) = v;
                } else {
                    *reinterpret_cast<float2*>((float*)C + (size_t)rr * N + col) =
                        make_float2(x0, x1);
                }
            }
        }
    }
}

__global__ void gemm_tc_f32(const __nv_bfloat16* __restrict__ A,
                            const __nv_bfloat16* __restrict__ Bt,
                            const float* __restrict__ bias,
                            float* __restrict__ C, int M, int N, int K)
{
    gemm_tc_body<float>(A, Bt, bias, C, M, N, K);
}

__global__ void gemm_tc_qkv0(const __nv_bfloat16* __restrict__ A, size_t sA,
                             const __nv_bfloat16* __restrict__ Bt, size_t sB,
                             __nv_bfloat16* __restrict__ C, size_t sC,
                             int M, int N, int K)
{
    int z = blockIdx.z;
    int r = z % R_NUM;
    gemm_tc_body<__nv_bfloat16>(A + (size_t)r * sA, Bt + (size_t)z * sB, nullptr,
                                C + (size_t)z * sC, M, N, K);
}

__global__ void gemm_tc_batch_f32(const __nv_bfloat16* __restrict__ A, size_t sA,
                                  const __nv_bfloat16* __restrict__ Bt, size_t sB,
                                  float* __restrict__ C, size_t sC,
                                  int M, int N, int K)
{
    int r = blockIdx.z;
    gemm_tc_body<float>(A + (size_t)r * sA, Bt + (size_t)r * sB, nullptr,
                        C + (size_t)r * sC, M, N, K);
}

// ---------------- gather ----------------
__global__ void gather_bf(const float* __restrict__ emb,
                          const int* __restrict__ n_id,
                          const int* __restrict__ lni,
                          __nv_bfloat16* __restrict__ xbf)
{
    int i = blockIdx.x * blockDim.x + threadIdx.x;
    if (i >= N1T * 32) return;
    int n = i >> 5, d = i & 31;
    int row = lni[n_id[n]];
    float4 v = reinterpret_cast<const float4*>(emb)[(size_t)row * 32 + d];
    __nv_bfloat162 lo = __floats2bfloat162_rn(v.x, v.y);
    __nv_bfloat162 hi = __floats2bfloat162_rn(v.z, v.w);
    uint2 pk;
    pk.x = *reinterpret_cast<unsigned*>(&lo);
    pk.y = *reinterpret_cast<unsigned*>(&hi);
    reinterpret_cast<uint2*>(xbf)[(size_t)n * 32 + d] = pk;
}

// ---------------- mega prep: all weight conversions + zero-fills ----------------
#define B_S0 384
#define B_S1 3840
#define B_S2 120
#define B_S3 150
#define B_S4 293
#define B_S5 9375
#define B_S6 74
#define B_S7 1465
#define B_TOT (B_S0+B_S1+B_S2+B_S3+B_S4+B_S5+B_S6+B_S7)

__global__ void mega_prep(const float* __restrict__ Wj0, const float* __restrict__ Wi0,
                          const float* __restrict__ sw0, const float* __restrict__ sb0,
                          const float* __restrict__ Wq0, const float* __restrict__ Wk0,
                          const float* __restrict__ Wv0,
                          const float* __restrict__ Wj1, const float* __restrict__ Wi1,
                          const float* __restrict__ sw1, const float* __restrict__ sb1,
                          const float* __restrict__ Wq1, const float* __restrict__ Wk1,
                          const float* __restrict__ Wv1,
                          __nv_bfloat16* __restrict__ wj0t, __nv_bfloat16* __restrict__ w0pack,
                          float* __restrict__ b0pack,
                          __nv_bfloat16* __restrict__ wqkv0t,
                          __nv_bfloat16* __restrict__ w1pack, float* __restrict__ b1pack,
                          __nv_bfloat16* __restrict__ wqkv1t,
                          uint4* __restrict__ den0z, uint4* __restrict__ z0z,
                          uint4* __restrict__ den1z, uint4* __restrict__ z1z)
{
    int b = blockIdx.x;
    int t = threadIdx.x;
    const uint4 zero4 = make_uint4(0u, 0u, 0u, 0u);

    if (b < B_S0) {
        int z = b >> 7;
        int i = ((b & 127) << 8) + t;
        int k = i >> 8, n = i & 255;
        const float* src = (z == 0) ? Wj0 : (z == 1) ? Wi0 : sw0;
        __nv_bfloat16 v = __float2bfloat16(src[i]);
        if (z == 0) {
            wj0t[(size_t)n * IN_DIM + k] = v;
            if (i < 256) b0pack[i] = 0.f;
        } else {
            int off = (z == 2) ? 256 : 0;
            w0pack[((size_t)(off + n)) * IN_DIM + k] = v;
            if (z == 2 && i < 256) b0pack[256 + i] = sb0[i];
        }
        return;
    }
    b -= B_S0;
    if (b < B_S1) {
        int z = b >> 8;
        int i = ((b & 255) << 8) + t;
        int which = z / R_NUM, r = z % R_NUM;
        const float* src = ((which == 0) ? Wq0 : (which == 1) ? Wk0 : Wv0)
                           + (size_t)r * HC0 * HC0;
        int k = i >> 8, n = i & 255;
        wqkv0t[(size_t)z * HC0 * HC0 + (size_t)n * HC0 + k] = __float2bfloat16(src[i]);
        return;
    }
    b -= B_S1;
    if (b < B_S2) {
        int z = b / 40;
        int i = (b % 40) * 256 + t;
        int k = i / C1, col = i - k * C1;
        const float* src = (z == 0) ? Wj1 : (z == 1) ? Wi1 : sw1;
        w1pack[(size_t)(z * C1 + col) * HC0 + k] = __float2bfloat16(src[i]);
        if (z == 0 && i < 80) b1pack[i] = 0.f;
        if (z == 2 && i < C1) b1pack[80 + i] = sb1[i];
        return;
    }
    b -= B_S2;
    if (b < B_S3) {
        int r = b / 30;
        int i = (b % 30) * 256 + t;
        int n = i >> 6, k = i & 63;
        int which = n / C1, col = n - which * C1;
        float v = 0.f;
        if (k < C1) {
            const float* src = ((which == 0) ? Wq1 : (which == 1) ? Wk1 : Wv1)
                               + (size_t)r * C1 * C1;
            v = src[k * C1 + col];
        }
        wqkv1t[(size_t)r * 120 * 64 + i] = __float2bfloat16(v);
        return;
    }
    b -= B_S3;
    if (b < B_S4) {
        int i = (b << 8) + t;
        if (i < 75000) den0z[i] = zero4;
        return;
    }
    b -= B_S4;
    if (b < B_S5) {
        int i = (b << 8) + t;
        z0z[i] = zero4;
        return;
    }
    b -= B_S5;
    if (b < B_S6) {
        int i = (b << 8) + t;
        if (i < 18750) den1z[i] = zero4;
        return;
    }
    b -= B_S6;
    {
        int i = (b << 8) + t;
        if (i < 375000) z1z[i] = zero4;
    }
}

// ---------------- fused edge kernels (unnormalized scatter, v4 red) ----------------
__global__ void edge_fused0(const int* __restrict__ src, const int* __restrict__ tgt,
                            const int* __restrict__ et,
                            const float* __restrict__ hj,
                            const float* __restrict__ hall,
                            const float* __restrict__ attj, const float* __restrict__ atti,
                            float* __restrict__ den, __nv_bfloat16* __restrict__ z,
                            int E)
{
    int w = (blockIdx.x * blockDim.x + threadIdx.x) >> 5;
    int lane = threadIdx.x & 31;
    if (w >= E) return;
    int gn = tgt[w];
    if (gn >= N2T) return;
    int t = et[w], s = src[w];
    const float* hjr = hj + (size_t)s * 256;
    const float* hir = hall + (size_t)gn * 512;
    int h = lane >> 3, j = lane & 7;
    const float* ajh = attj + ((size_t)t * 4 + h) * 64;
    const float* aih = atti + ((size_t)t * 4 + h) * 64;
    float acc = 0.f;
#pragma unroll
    for (int u = 0; u < 8; u++) {
        int c = j + 8 * u;
        acc += ajh[c] * hjr[h * 64 + c] + aih[c] * hir[h * 64 + c];
    }
#pragma unroll
    for (int o = 4; o; o >>= 1) acc += __shfl_xor_sync(0xffffffffu, acc, o);
    float a = acc >= 0.f ? acc : 0.2f * acc;
    float ex = expf(a);
    if (j == 0) atomicAdd(&den[((size_t)gn * R_NUM + t) * 4 + h], ex);
    // head for this lane's 8 values [8*lane, 8*lane+8): h = lane>>3 (same h as logit work)
    float e = __shfl_sync(0xffffffffu, ex, (lane >> 3) * 8);
    const float* hv = hjr + 8 * lane;
    __nv_bfloat162 p0 = __floats2bfloat162_rn(e * hv[0], e * hv[1]);
    __nv_bfloat162 p1 = __floats2bfloat162_rn(e * hv[2], e * hv[3]);
    __nv_bfloat162 p2 = __floats2bfloat162_rn(e * hv[4], e * hv[5]);
    __nv_bfloat162 p3 = __floats2bfloat162_rn(e * hv[6], e * hv[7]);
    uint4* zr4 = reinterpret_cast<uint4*>(z + ((size_t)t * N2T + gn) * 256) + lane;
    red_v4_bf16x2(zr4,
                  *reinterpret_cast<unsigned*>(&p0), *reinterpret_cast<unsigned*>(&p1),
                  *reinterpret_cast<unsigned*>(&p2), *reinterpret_cast<unsigned*>(&p3));
}

__global__ void edge_fused1(const int* __restrict__ src, const int* __restrict__ tgt,
                            const int* __restrict__ et,
                            const float* __restrict__ hall,
                            const float* __restrict__ attj, const float* __restrict__ atti,
                            float* __restrict__ den, __nv_bfloat16* __restrict__ z,
                            int E)
{
    int w = (blockIdx.x * blockDim.x + threadIdx.x) >> 5;
    int lane = threadIdx.x & 31;
    if (w >= E) return;
    int gn = tgt[w];
    int t = et[w], s = src[w];
    const float* hjr = hall + (size_t)s * 120;
    const float* hir = hall + (size_t)gn * 120 + 40;
    const float* aj = attj + (size_t)t * 40;
    const float* ai = atti + (size_t)t * 40;
    float acc = aj[lane] * hjr[lane] + ai[lane] * hir[lane];
    if (lane < 8) acc += aj[lane + 32] * hjr[lane + 32] + ai[lane + 32] * hir[lane + 32];
#pragma unroll
    for (int o = 16; o; o >>= 1) acc += __shfl_xor_sync(0xffffffffu, acc, o);
    float a = acc >= 0.f ? acc : 0.2f * acc;
    float ex = expf(a);
    if (lane == 0) atomicAdd(&den[(size_t)gn * R_NUM + t], ex);
    if (lane < 5) {
        const float* hv = hjr + 8 * lane;
        __nv_bfloat162 p0 = __floats2bfloat162_rn(ex * hv[0], ex * hv[1]);
        __nv_bfloat162 p1 = __floats2bfloat162_rn(ex * hv[2], ex * hv[3]);
        __nv_bfloat162 p2 = __floats2bfloat162_rn(ex * hv[4], ex * hv[5]);
        __nv_bfloat162 p3 = __floats2bfloat162_rn(ex * hv[6], ex * hv[7]);
        uint4* zr4 = reinterpret_cast<uint4*>(z + ((size_t)t * N2T + gn) * 40) + lane;
        red_v4_bf16x2(zr4,
                      *reinterpret_cast<unsigned*>(&p0), *reinterpret_cast<unsigned*>(&p1),
                      *reinterpret_cast<unsigned*>(&p2), *reinterpret_cast<unsigned*>(&p3));
    }
}

// ---------------- normalize / pad ----------------
__global__ void z0_norm(__nv_bfloat162* __restrict__ z, const float* __restrict__ den)
{
    size_t i = (size_t)blockIdx.x * 256 + threadIdx.x;
    const size_t tot = (size_t)R_NUM * N2T * 128;
    if (i >= tot) return;
    int c2 = i & 127;
    size_t row = i >> 7;
    int r = row / N2T; int n = (int)(row - (size_t)r * N2T);
    int h = c2 >> 5;
    float d = fmaxf(den[((size_t)n * R_NUM + r) * 4 + h], 1e-16f);
    float inv = __fdividef(1.f, d);
    __nv_bfloat162 v = z[i];
    z[i] = __floats2bfloat162_rn(__low2float(v) * inv, __high2float(v) * inv);
}

__global__ void z1_pad(const __nv_bfloat16* __restrict__ z, const float* __restrict__ den,
                       __nv_bfloat16* __restrict__ out)
{
    int i = blockIdx.x * 256 + threadIdx.x;
    const int tot = R_NUM * N2T * 64;
    if (i >= tot) return;
    int c = i & 63;
    int row = i >> 6;
    int r = row / N2T; int n = row - r * N2T;
    float v = 0.f;
    if (c < 40) {
        float inv = __fdividef(1.f, fmaxf(den[(size_t)n * R_NUM + r], 1e-16f));
        v = __bfloat162float(z[(size_t)row * 40 + c]) * inv;
    }
    out[i] = __float2bfloat16(v);
}

// ---------------- bilevel relation attention ----------------
__device__ __forceinline__ void relcoeff(const float psi[R_NUM][R_NUM],
                                         const float* wrel, float coeff[R_NUM])
{
#pragma unroll
    for (int s = 0; s < R_NUM; s++) coeff[s] = 0.f;
#pragma unroll
    for (int r = 0; r < R_NUM; r++) {
        float rsum = 0.f;
#pragma unroll
        for (int s = 0; s < R_NUM; s++) rsum += psi[r][s];
        float pv[R_NUM], mx = -INFINITY;
#pragma unroll
        for (int s = 0; s < R_NUM; s++) {
            float xx = psi[r][s];
            bool masked = (xx == 0.f) && (rsum != 0.f);
            pv[s] = masked ? -INFINITY : xx;
            mx = fmaxf(mx, pv[s]);
        }
        float pe[R_NUM], se = 0.f;
#pragma unroll
        for (int s = 0; s < R_NUM; s++) {
            float e = isinf(pv[s]) ? 0.f : expf(pv[s] - mx);
            pe[s] = e; se += e;
        }
        float inv = wrel[r] / se;
#pragma unroll
        for (int s = 0; s < R_NUM; s++) coeff[s] += pe[s] * inv;
    }
}

__global__ void attn0_kernel(const __nv_bfloat16* __restrict__ q,
                             const __nv_bfloat16* __restrict__ k,
                             const __nv_bfloat16* __restrict__ v,
                             const float* __restrict__ wrel,
                             const float* __restrict__ hall,
                             __nv_bfloat16* __restrict__ outbf)
{
    int w = (blockIdx.x * blockDim.x + threadIdx.x) >> 5;
    int lane = threadIdx.x & 31;
    if (w >= N2T * 4) return;
    int n = w >> 2, h = w & 3;
    size_t base = (size_t)n * 256 + h * 64;
    const size_t rst = (size_t)N2T * 256;
    int c0 = lane, c1 = lane + 32;

    float qv[R_NUM][2], kv[R_NUM][2], vv[R_NUM][2];
#pragma unroll
    for (int r = 0; r < R_NUM; r++) {
        size_t o = (size_t)r * rst + base;
        qv[r][0] = __bfloat162float(q[o + c0]); qv[r][1] = __bfloat162float(q[o + c1]);
        kv[r][0] = __bfloat162float(k[o + c0]); kv[r][1] = __bfloat162float(k[o + c1]);
        vv[r][0] = __bfloat162float(v[o + c0]); vv[r][1] = __bfloat162float(v[o + c1]);
    }
    float psi[R_NUM][R_NUM];
#pragma unroll
    for (int r = 0; r < R_NUM; r++)
#pragma unroll
        for (int s = 0; s < R_NUM; s++) {
            float p = qv[r][0] * kv[s][0] + qv[r][1] * kv[s][1];
#pragma unroll
            for (int o = 16; o; o >>= 1) p += __shfl_xor_sync(0xffffffffu, p, o);
            psi[r][s] = p;
        }
    float coeff[R_NUM];
    relcoeff(psi, wrel, coeff);

    const float* self = hall + (size_t)n * 512 + 256 + h * 64;
#pragma unroll
    for (int jj = 0; jj < 2; jj++) {
        int c = lane + 32 * jj;
        float acc = 0.f;
#pragma unroll
        for (int s = 0; s < R_NUM; s++) acc += coeff[s] * vv[s][jj];
        float val = self[c] + acc;
        outbf[base + c] = __float2bfloat16(fmaxf(val, 0.f));
    }
}

__global__ void attn1_ls(const float* __restrict__ qkv, const float* __restrict__ wrel,
                         const float* __restrict__ hall, float* __restrict__ out)
{
    int w = (blockIdx.x * blockDim.x + threadIdx.x) >> 5;
    int lane = threadIdx.x & 31;
    if (w >= N2T) return;
    int n = w;
    const size_t rst = (size_t)N2T * 120;
    size_t base = (size_t)n * 120;
    bool ok1 = lane < 8;

    float qv[R_NUM][2], kv[R_NUM][2], vv[R_NUM][2];
#pragma unroll
    for (int r = 0; r < R_NUM; r++) {
        const float* p = qkv + (size_t)r * rst + base;
        qv[r][0] = p[lane];      qv[r][1] = ok1 ? p[32 + lane] : 0.f;
        kv[r][0] = p[40 + lane]; kv[r][1] = ok1 ? p[72 + lane] : 0.f;
        vv[r][0] = p[80 + lane]; vv[r][1] = ok1 ? p[112 + lane] : 0.f;
    }
    float psi[R_NUM][R_NUM];
#pragma unroll
    for (int r = 0; r < R_NUM; r++)
#pragma unroll
        for (int s = 0; s < R_NUM; s++) {
            float p = qv[r][0] * kv[s][0] + qv[r][1] * kv[s][1];
#pragma unroll
            for (int o = 16; o; o >>= 1) p += __shfl_xor_sync(0xffffffffu, p, o);
            psi[r][s] = p;
        }
    float coeff[R_NUM];
    relcoeff(psi, wrel, coeff);

    const float* self = hall + (size_t)n * 120 + 80;
    float a0 = 0.f, a1 = 0.f;
#pragma unroll
    for (int s = 0; s < R_NUM; s++) { a0 += coeff[s] * vv[s][0]; a1 += coeff[s] * vv[s][1]; }
    float v0 = self[lane] + a0;
    float v1 = ok1 ? self[32 + lane] + a1 : -INFINITY;

    float mx = fmaxf(v0, v1);
#pragma unroll
    for (int o = 16; o; o >>= 1) mx = fmaxf(mx, __shfl_xor_sync(0xffffffffu, mx, o));
    float se = expf(v0 - mx) + (ok1 ? expf(v1 - mx) : 0.f);
#pragma unroll
    for (int o = 16; o; o >>= 1) se += __shfl_xor_sync(0xffffffffu, se, o);
    float lse = mx + logf(se);
    out[(size_t)n * 40 + lane] = v0 - lse;
    if (ok1) out[(size_t)n * 40 + 32 + lane] = v1 - lse;
}

// ---------------- host ----------------
extern "C" void kernel_launch(void* const* d_in, const int* in_sizes, int n_in,
                              void* d_out, int out_size)
{
    const int*   n_id  = (const int*)d_in[0];
    const int*   lni   = (const int*)d_in[1];
    const int*   ei0   = (const int*)d_in[3];
    const int*   et0   = (const int*)d_in[4];
    const int*   ei1   = (const int*)d_in[5];
    const int*   et1   = (const int*)d_in[6];
    const float* emb   = (const float*)d_in[7];
    const float* Wj0   = (const float*)d_in[8];
    const float* Wi0   = (const float*)d_in[9];
    const float* attj0 = (const float*)d_in[10];
    const float* atti0 = (const float*)d_in[11];
    const float* Wq0   = (const float*)d_in[12];
    const float* Wk0   = (const float*)d_in[13];
    const float* Wv0   = (const float*)d_in[14];
    const float* sw0   = (const float*)d_in[15];
    const float* sb0   = (const float*)d_in[16];
    const float* Wrel0 = (const float*)d_in[17];
    const float* Wj1   = (const float*)d_in[18];
    const float* Wi1   = (const float*)d_in[19];
    const float* attj1 = (const float*)d_in[20];
    const float* atti1 = (const float*)d_in[21];
    const float* Wq1   = (const float*)d_in[22];
    const float* Wk1   = (const float*)d_in[23];
    const float* Wv1   = (const float*)d_in[24];
    const float* sw1   = (const float*)d_in[25];
    const float* sb1   = (const float*)d_in[26];
    const float* Wrel1 = (const float*)d_in[27];

    int E0 = in_sizes[4];
    int E1 = in_sizes[6];

    __nv_bfloat16 *xbf, *z0bf, *qkv0bf, *x1bf, *z1bf, *z1p;
    __nv_bfloat16 *wj0t, *w0pack, *wqkv0t, *w1pack, *wqkv1t;
    float *hj0, *h0all, *den0, *h1all, *den1, *qkv1, *b0pack, *b1pack;
    cudaGetSymbolAddress((void**)&xbf,    g_xbf);
    cudaGetSymbolAddress((void**)&hj0,    g_hj0);
    cudaGetSymbolAddress((void**)&h0all,  g_h0all);
    cudaGetSymbolAddress((void**)&den0,   g_den0);
    cudaGetSymbolAddress((void**)&z0bf,   g_z0bf);
    cudaGetSymbolAddress((void**)&qkv0bf, g_qkv0bf);
    cudaGetSymbolAddress((void**)&x1bf,   g_x1bf);
    cudaGetSymbolAddress((void**)&h1all,  g_h1all);
    cudaGetSymbolAddress((void**)&den1,   g_den1);
    cudaGetSymbolAddress((void**)&z1bf,   g_z1bf);
    cudaGetSymbolAddress((void**)&z1p,    g_z1p);
    cudaGetSymbolAddress((void**)&qkv1,   g_qkv1);
    cudaGetSymbolAddress((void**)&wj0t,   g_wj0t);
    cudaGetSymbolAddress((void**)&w0pack, g_w0pack);
    cudaGetSymbolAddress((void**)&b0pack, g_b0pack);
    cudaGetSymbolAddress((void**)&wqkv0t, g_wqkv0t);
    cudaGetSymbolAddress((void**)&w1pack, g_w1pack);
    cudaGetSymbolAddress((void**)&b1pack, g_b1pack);
    cudaGetSymbolAddress((void**)&wqkv1t, g_wqkv1t);

    // ---- prep (weights + zero-fills) + gather ----
    mega_prep<<<B_TOT, 256>>>(Wj0, Wi0, sw0, sb0, Wq0, Wk0, Wv0,
                              Wj1, Wi1, sw1, sb1, Wq1, Wk1, Wv1,
                              wj0t, w0pack, b0pack, wqkv0t, w1pack, b1pack, wqkv1t,
                              (uint4*)den0, (uint4*)z0bf, (uint4*)den1, (uint4*)z1bf);
    gather_bf<<<cdiv(N1T * 32, 256), 256>>>(emb, n_id, lni, xbf);

    // ---- layer 0 ----
    gemm_tc_f32<<<dim3(2, cdiv(N1T, TBM)), 256>>>(xbf, wj0t, nullptr, hj0, N1T, 256, IN_DIM);
    gemm_tc_f32<<<dim3(4, cdiv(N2T, TBM)), 256>>>(xbf, w0pack, b0pack, h0all, N2T, 512, IN_DIM);

    edge_fused0<<<cdiv(E0 * 32, 256), 256>>>(ei0, ei0 + E0, et0, hj0, h0all,
                                             attj0, atti0, den0, z0bf, E0);
    z0_norm<<<cdiv(R_NUM * N2T * 128, 256), 256>>>((__nv_bfloat162*)z0bf, den0);

    gemm_tc_qkv0<<<dim3(2, cdiv(N2T, TBM), 15), 256>>>(
        z0bf, (size_t)N2T * HC0,
        wqkv0t, (size_t)HC0 * HC0,
        qkv0bf, (size_t)N2T * HC0,
        N2T, HC0, HC0);

    {
        const __nv_bfloat16* q0 = qkv0bf;
        const __nv_bfloat16* k0 = qkv0bf + (size_t)R_NUM * N2T * HC0;
        const __nv_bfloat16* v0 = qkv0bf + (size_t)2 * R_NUM * N2T * HC0;
        attn0_kernel<<<cdiv(N2T * 4 * 32, 256), 256>>>(q0, k0, v0, Wrel0, h0all, x1bf);
    }

    // ---- layer 1 ----
    gemm_tc_f32<<<dim3(1, cdiv(N2T, TBM)), 256>>>(x1bf, w1pack, b1pack, h1all, N2T, 120, HC0);

    edge_fused1<<<cdiv(E1 * 32, 256), 256>>>(ei1, ei1 + E1, et1, h1all,
                                             attj1, atti1, den1, z1bf, E1);
    z1_pad<<<cdiv(R_NUM * N2T * 64, 256), 256>>>(z1bf, den1, z1p);

    gemm_tc_batch_f32<<<dim3(1, cdiv(N2T, TBM), R_NUM), 256>>>(
        z1p, (size_t)N2T * 64,
        wqkv1t, (size_t)120 * 64,
        qkv1, (size_t)N2T * 120,
        N2T, 120, 64);

    attn1_ls<<<cdiv(N2T * 32, 256), 256>>>(qkv1, Wrel1, h1all, (float*)d_out);
}

// round 17
// speedup vs baseline: 1.0056x; 1.0056x over previous
#include <cuda_runtime.h>
#include <cuda_bf16.h>
#include <math.h>

// ---------------- problem constants ----------------
#define R_NUM 5
#define N1T   30000
#define N2T   15000
#define IN_DIM 128
#define HC0   256
#define H0    4
#define C0    64
#define HC1   40
#define C1    40
#define E0MAX 300000
#define E1MAX 150000

// ---------------- scratch ----------------
__device__ __nv_bfloat16 g_xbf [(size_t)N1T * IN_DIM];
__device__ float g_hj0 [(size_t)N1T * HC0];
__device__ float g_h0all[(size_t)N2T * 512];              // [hi0 | x1self+bias]
__device__ float g_den0[(size_t)N2T * R_NUM * H0];
__device__ __nv_bfloat16 g_z0bf[(size_t)R_NUM * N2T * HC0];
__device__ __nv_bfloat16 g_qkv0bf[(size_t)3 * R_NUM * N2T * HC0]; // q|k|v
__device__ __nv_bfloat16 g_x1bf[(size_t)N2T * HC0];
__device__ float g_h1all[(size_t)N2T * 120];              // [hj1 | hi1 | o1self+bias]
__device__ float g_den1[(size_t)N2T * R_NUM];
__device__ __nv_bfloat16 g_z1bf[(size_t)R_NUM * N2T * HC1];
__device__ __nv_bfloat16 g_z1p [(size_t)R_NUM * N2T * 64];
__device__ float g_qkv1[(size_t)R_NUM * N2T * 120];
// weights (transposed / packed, bf16)
__device__ __nv_bfloat16 g_wj0t  [(size_t)HC0 * IN_DIM];
__device__ __nv_bfloat16 g_w0pack[(size_t)512 * IN_DIM];
__device__ float         g_b0pack[512];
__device__ __nv_bfloat16 g_wqkv0t[(size_t)3 * R_NUM * HC0 * HC0];
__device__ __nv_bfloat16 g_w1pack[(size_t)120 * HC0];
__device__ float         g_b1pack[120];
__device__ __nv_bfloat16 g_wqkv1t[(size_t)R_NUM * 120 * 64];

static inline int cdiv(int a, int b) { return (a + b - 1) / b; }

// ---------------- cp.async helpers ----------------
__device__ __forceinline__ void cp16(void* dst, const void* src, bool ok) {
    unsigned d = (unsigned)__cvta_generic_to_shared(dst);
    int n = ok ? 16 : 0;
    asm volatile("cp.async.cg.shared.global [%0], [%1], 16, %2;\n"
                 :: "r"(d), "l"(src), "r"(n));
}
__device__ __forceinline__ void cp_commit() {
    asm volatile("cp.async.commit_group;\n");
}
template <int N> __device__ __forceinline__ void cp_wait() {
    asm volatile("cp.async.wait_group %0;\n" :: "n"(N));
}

// ---------------- bf16 tensor-core GEMM (round-5 proven body) ----------------
__device__ __forceinline__ void mma16816(float* d, const unsigned* a,
                                         const unsigned* b, const float* c)
{
    asm volatile(
        "mma.sync.aligned.m16n8k16.row.col.f32.bf16.bf16.f32 "
        "{%0,%1,%2,%3}, {%4,%5,%6,%7}, {%8,%9}, {%10,%11,%12,%13};\n"
        : "=f"(d[0]), "=f"(d[1]), "=f"(d[2]), "=f"(d[3])
        : "r"(a[0]), "r"(a[1]), "r"(a[2]), "r"(a[3]),
          "r"(b[0]), "r"(b[1]),
          "f"(c[0]), "f"(c[1]), "f"(c[2]), "f"(c[3]));
}

#define TBM 128
#define TBN 128
#define TLD 40

// C[M,N] = A[M,K](bf16 rm) @ Bt[N,K](bf16) (+bias). 3-stage cp.async pipeline.
template <typename OT>
__device__ __forceinline__ void gemm_tc_body(const __nv_bfloat16* __restrict__ A,
                                             const __nv_bfloat16* __restrict__ Bt,
                                             const float* __restrict__ bias,
                                             OT* __restrict__ C,
                                             int M, int N, int K)
{
    __shared__ __nv_bfloat16 As[3][TBM * TLD];
    __shared__ __nv_bfloat16 Bs[3][TBN * TLD];
    int tid = threadIdx.x;
    int wid = tid >> 5, lane = tid & 31;
    int wm = wid >> 1, wn = wid & 1;
    int m0 = blockIdx.y * TBM, n0 = blockIdx.x * TBN;
    int g = lane >> 2, cq = lane & 3;
    int r0 = tid >> 2, kg = (tid & 3) * 8;

    float acc[2][8][4];
#pragma unroll
    for (int i = 0; i < 2; i++)
#pragma unroll
        for (int j = 0; j < 8; j++)
#pragma unroll
            for (int q = 0; q < 4; q++) acc[i][j][q] = 0.f;

    int nt = K >> 5;

    auto load_stage = [&](int s, int kt, bool active) {
        if (active) {
#pragma unroll
            for (int it = 0; it < 2; it++) {
                int r = r0 + it * 64;
                bool okA = (m0 + r) < M;
                bool okB = (n0 + r) < N;
                const __nv_bfloat16* pa = A + (size_t)(okA ? (m0 + r) : 0) * K + kt + kg;
                const __nv_bfloat16* pb = Bt + (size_t)(okB ? (n0 + r) : 0) * K + kt + kg;
                cp16(&As[s][r * TLD + kg], pa, okA);
                cp16(&Bs[s][r * TLD + kg], pb, okB);
            }
        }
        cp_commit();
    };

    load_stage(0, 0, true);
    load_stage(1, 32, nt > 1);

    for (int i = 0; i < nt; i++) {
        load_stage((i + 2) % 3, (i + 2) << 5, (i + 2) < nt);
        cp_wait<2>();
        __syncthreads();
        int s = i % 3;
#pragma unroll
        for (int ks = 0; ks < 2; ks++) {
            int kb = ks * 16;
            unsigned a[2][4], b[8][2];
#pragma unroll
            for (int mf = 0; mf < 2; mf++) {
                const __nv_bfloat16* p = &As[s][(wm * 32 + mf * 16 + g) * TLD + kb + cq * 2];
                a[mf][0] = *reinterpret_cast<const unsigned*>(p);
                a[mf][1] = *reinterpret_cast<const unsigned*>(p + 8 * TLD);
                a[mf][2] = *reinterpret_cast<const unsigned*>(p + 8);
                a[mf][3] = *reinterpret_cast<const unsigned*>(p + 8 * TLD + 8);
            }
#pragma unroll
            for (int nf = 0; nf < 8; nf++) {
                const __nv_bfloat16* p = &Bs[s][(wn * 64 + nf * 8 + g) * TLD + kb + cq * 2];
                b[nf][0] = *reinterpret_cast<const unsigned*>(p);
                b[nf][1] = *reinterpret_cast<const unsigned*>(p + 8);
            }
#pragma unroll
            for (int mf = 0; mf < 2; mf++)
#pragma unroll
                for (int nf = 0; nf < 8; nf++)
                    mma16816(acc[mf][nf], a[mf], b[nf], acc[mf][nf]);
        }
        __syncthreads();
    }

#pragma unroll
    for (int mf = 0; mf < 2; mf++) {
#pragma unroll
        for (int nf = 0; nf < 8; nf++) {
            int col = n0 + wn * 64 + nf * 8 + cq * 2;
            int row = m0 + wm * 32 + mf * 16 + g;
            if (col >= N) continue;
            float b0 = 0.f, b1 = 0.f;
            if (bias) { b0 = bias[col]; b1 = bias[col + 1]; }
#pragma unroll
            for (int half = 0; half < 2; half++) {
                int rr = row + half * 8;
                if (rr >= M) continue;
                float x0 = acc[mf][nf][half * 2 + 0] + b0;
                float x1 = acc[mf][nf][half * 2 + 1] + b1;
                if constexpr (sizeof(OT) == 2) {
                    __nv_bfloat162 v = __floats2bfloat162_rn(x0, x1);
                    *reinterpret_cast<__nv_bfloat162*>(
                        (__nv_bfloat16*)C + (size_t)rr * N + col) = v;
                } else {
                    *reinterpret_cast<float2*>((float*)C + (size_t)rr * N + col) =
                        make_float2(x0, x1);
                }
            }
        }
    }
}

__global__ void gemm_tc_f32(const __nv_bfloat16* __restrict__ A,
                            const __nv_bfloat16* __restrict__ Bt,
                            const float* __restrict__ bias,
                            float* __restrict__ C, int M, int N, int K)
{
    gemm_tc_body<float>(A, Bt, bias, C, M, N, K);
}

// qkv0: A shared per relation r; z = which*5 + r. bf16 output.
__global__ void gemm_tc_qkv0(const __nv_bfloat16* __restrict__ A, size_t sA,
                             const __nv_bfloat16* __restrict__ Bt, size_t sB,
                             __nv_bfloat16* __restrict__ C, size_t sC,
                             int M, int N, int K)
{
    int z = blockIdx.z;
    int r = z % R_NUM;
    gemm_tc_body<__nv_bfloat16>(A + (size_t)r * sA, Bt + (size_t)z * sB, nullptr,
                                C + (size_t)z * sC, M, N, K);
}

__global__ void gemm_tc_batch_f32(const __nv_bfloat16* __restrict__ A, size_t sA,
                                  const __nv_bfloat16* __restrict__ Bt, size_t sB,
                                  float* __restrict__ C, size_t sC,
                                  int M, int N, int K)
{
    int r = blockIdx.z;
    gemm_tc_body<float>(A + (size_t)r * sA, Bt + (size_t)r * sB, nullptr,
                        C + (size_t)r * sC, M, N, K);
}

// ---------------- gather ----------------
__global__ void gather_bf(const float* __restrict__ emb,
                          const int* __restrict__ n_id,
                          const int* __restrict__ lni,
                          __nv_bfloat16* __restrict__ xbf)
{
    int i = blockIdx.x * blockDim.x + threadIdx.x;
    if (i >= N1T * 32) return;
    int n = i >> 5, d = i & 31;
    int row = lni[n_id[n]];
    float4 v = reinterpret_cast<const float4*>(emb)[(size_t)row * 32 + d];
    __nv_bfloat162 lo = __floats2bfloat162_rn(v.x, v.y);
    __nv_bfloat162 hi = __floats2bfloat162_rn(v.z, v.w);
    uint2 pk;
    pk.x = *reinterpret_cast<unsigned*>(&lo);
    pk.y = *reinterpret_cast<unsigned*>(&hi);
    reinterpret_cast<uint2*>(xbf)[(size_t)n * 32 + d] = pk;
}

// ---------------- mega prep: all weight conversions + zero-fills ----------------
#define B_S0 384
#define B_S1 3840
#define B_S2 120
#define B_S3 150
#define B_S4 293
#define B_S5 9375
#define B_S6 74
#define B_S7 1465
#define B_TOT (B_S0+B_S1+B_S2+B_S3+B_S4+B_S5+B_S6+B_S7)

__global__ void mega_prep(const float* __restrict__ Wj0, const float* __restrict__ Wi0,
                          const float* __restrict__ sw0, const float* __restrict__ sb0,
                          const float* __restrict__ Wq0, const float* __restrict__ Wk0,
                          const float* __restrict__ Wv0,
                          const float* __restrict__ Wj1, const float* __restrict__ Wi1,
                          const float* __restrict__ sw1, const float* __restrict__ sb1,
                          const float* __restrict__ Wq1, const float* __restrict__ Wk1,
                          const float* __restrict__ Wv1,
                          __nv_bfloat16* __restrict__ wj0t, __nv_bfloat16* __restrict__ w0pack,
                          float* __restrict__ b0pack,
                          __nv_bfloat16* __restrict__ wqkv0t,
                          __nv_bfloat16* __restrict__ w1pack, float* __restrict__ b1pack,
                          __nv_bfloat16* __restrict__ wqkv1t,
                          uint4* __restrict__ den0z, uint4* __restrict__ z0z,
                          uint4* __restrict__ den1z, uint4* __restrict__ z1z)
{
    int b = blockIdx.x;
    int t = threadIdx.x;
    const uint4 zero4 = make_uint4(0u, 0u, 0u, 0u);

    if (b < B_S0) {
        int z = b >> 7;
        int i = ((b & 127) << 8) + t;
        int k = i >> 8, n = i & 255;
        const float* src = (z == 0) ? Wj0 : (z == 1) ? Wi0 : sw0;
        __nv_bfloat16 v = __float2bfloat16(src[i]);
        if (z == 0) {
            wj0t[(size_t)n * IN_DIM + k] = v;
            if (i < 256) b0pack[i] = 0.f;
        } else {
            int off = (z == 2) ? 256 : 0;
            w0pack[((size_t)(off + n)) * IN_DIM + k] = v;
            if (z == 2 && i < 256) b0pack[256 + i] = sb0[i];
        }
        return;
    }
    b -= B_S0;
    if (b < B_S1) {
        int z = b >> 8;
        int i = ((b & 255) << 8) + t;
        int which = z / R_NUM, r = z % R_NUM;
        const float* src = ((which == 0) ? Wq0 : (which == 1) ? Wk0 : Wv0)
                           + (size_t)r * HC0 * HC0;
        int k = i >> 8, n = i & 255;
        wqkv0t[(size_t)z * HC0 * HC0 + (size_t)n * HC0 + k] = __float2bfloat16(src[i]);
        return;
    }
    b -= B_S1;
    if (b < B_S2) {
        int z = b / 40;
        int i = (b % 40) * 256 + t;
        int k = i / C1, col = i - k * C1;
        const float* src = (z == 0) ? Wj1 : (z == 1) ? Wi1 : sw1;
        w1pack[(size_t)(z * C1 + col) * HC0 + k] = __float2bfloat16(src[i]);
        if (z == 0 && i < 80) b1pack[i] = 0.f;
        if (z == 2 && i < C1) b1pack[80 + i] = sb1[i];
        return;
    }
    b -= B_S2;
    if (b < B_S3) {
        int r = b / 30;
        int i = (b % 30) * 256 + t;
        int n = i >> 6, k = i & 63;
        int which = n / C1, col = n - which * C1;
        float v = 0.f;
        if (k < C1) {
            const float* src = ((which == 0) ? Wq1 : (which == 1) ? Wk1 : Wv1)
                               + (size_t)r * C1 * C1;
            v = src[k * C1 + col];
        }
        wqkv1t[(size_t)r * 120 * 64 + i] = __float2bfloat16(v);
        return;
    }
    b -= B_S3;
    if (b < B_S4) {
        int i = (b << 8) + t;
        if (i < 75000) den0z[i] = zero4;
        return;
    }
    b -= B_S4;
    if (b < B_S5) {
        int i = (b << 8) + t;
        z0z[i] = zero4;
        return;
    }
    b -= B_S5;
    if (b < B_S6) {
        int i = (b << 8) + t;
        if (i < 18750) den1z[i] = zero4;
        return;
    }
    b -= B_S6;
    {
        int i = (b << 8) + t;
        if (i < 375000) z1z[i] = zero4;
    }
}

// ---------------- fused edge kernels (unnormalized scatter, v4 red) --------
__device__ __forceinline__ void red_v4_bf16x2(void* addr, unsigned p0, unsigned p1,
                                              unsigned p2, unsigned p3)
{
    asm volatile("red.global.add.noftz.v4.bf16x2 [%0], {%1,%2,%3,%4};"
                 :: "l"(addr), "r"(p0), "r"(p1), "r"(p2), "r"(p3) : "memory");
}

__global__ void edge_fused0(const int* __restrict__ src, const int* __restrict__ tgt,
                            const int* __restrict__ et,
                            const float* __restrict__ hj,
                            const float* __restrict__ hall,
                            const float* __restrict__ attj, const float* __restrict__ atti,
                            float* __restrict__ den, __nv_bfloat16* __restrict__ z,
                            int E)
{
    int w = (blockIdx.x * blockDim.x + threadIdx.x) >> 5;
    int lane = threadIdx.x & 31;
    if (w >= E) return;
    int gn = tgt[w];
    if (gn >= N2T) return;
    int t = et[w], s = src[w];
    const float* hjr = hj + (size_t)s * 256;
    const float* hir = hall + (size_t)gn * 512;
    int h = lane >> 3, j = lane & 7;
    const float* ajh = attj + ((size_t)t * 4 + h) * 64;
    const float* aih = atti + ((size_t)t * 4 + h) * 64;
    float acc = 0.f;
#pragma unroll
    for (int u = 0; u < 8; u++) {
        int c = j + 8 * u;
        acc += ajh[c] * hjr[h * 64 + c] + aih[c] * hir[h * 64 + c];
    }
#pragma unroll
    for (int o = 4; o; o >>= 1) acc += __shfl_xor_sync(0xffffffffu, acc, o);
    float a = acc >= 0.f ? acc : 0.2f * acc;
    float ex = expf(a);
    if (j == 0) atomicAdd(&den[((size_t)gn * R_NUM + t) * 4 + h], ex);
    float e = __shfl_sync(0xffffffffu, ex, (lane >> 3) * 8);
    const float* hv = hjr + 8 * lane;
    __nv_bfloat162 p0 = __floats2bfloat162_rn(e * hv[0], e * hv[1]);
    __nv_bfloat162 p1 = __floats2bfloat162_rn(e * hv[2], e * hv[3]);
    __nv_bfloat162 p2 = __floats2bfloat162_rn(e * hv[4], e * hv[5]);
    __nv_bfloat162 p3 = __floats2bfloat162_rn(e * hv[6], e * hv[7]);
    uint4* zr4 = reinterpret_cast<uint4*>(z + ((size_t)t * N2T + gn) * 256) + lane;
    red_v4_bf16x2(zr4,
                  *reinterpret_cast<unsigned*>(&p0), *reinterpret_cast<unsigned*>(&p1),
                  *reinterpret_cast<unsigned*>(&p2), *reinterpret_cast<unsigned*>(&p3));
}

__global__ void edge_fused1(const int* __restrict__ src, const int* __restrict__ tgt,
                            const int* __restrict__ et,
                            const float* __restrict__ hall,
                            const float* __restrict__ attj, const float* __restrict__ atti,
                            float* __restrict__ den, __nv_bfloat16* __restrict__ z,
                            int E)
{
    int w = (blockIdx.x * blockDim.x + threadIdx.x) >> 5;
    int lane = threadIdx.x & 31;
    if (w >= E) return;
    int gn = tgt[w];
    int t = et[w], s = src[w];
    const float* hjr = hall + (size_t)s * 120;
    const float* hir = hall + (size_t)gn * 120 + 40;
    const float* aj = attj + (size_t)t * 40;
    const float* ai = atti + (size_t)t * 40;
    float acc = aj[lane] * hjr[lane] + ai[lane] * hir[lane];
    if (lane < 8) acc += aj[lane + 32] * hjr[lane + 32] + ai[lane + 32] * hir[lane + 32];
#pragma unroll
    for (int o = 16; o; o >>= 1) acc += __shfl_xor_sync(0xffffffffu, acc, o);
    float a = acc >= 0.f ? acc : 0.2f * acc;
    float ex = expf(a);
    if (lane == 0) atomicAdd(&den[(size_t)gn * R_NUM + t], ex);
    if (lane < 5) {
        const float* hv = hjr + 8 * lane;
        __nv_bfloat162 p0 = __floats2bfloat162_rn(ex * hv[0], ex * hv[1]);
        __nv_bfloat162 p1 = __floats2bfloat162_rn(ex * hv[2], ex * hv[3]);
        __nv_bfloat162 p2 = __floats2bfloat162_rn(ex * hv[4], ex * hv[5]);
        __nv_bfloat162 p3 = __floats2bfloat162_rn(ex * hv[6], ex * hv[7]);
        uint4* zr4 = reinterpret_cast<uint4*>(z + ((size_t)t * N2T + gn) * 40) + lane;
        red_v4_bf16x2(zr4,
                      *reinterpret_cast<unsigned*>(&p0), *reinterpret_cast<unsigned*>(&p1),
                      *reinterpret_cast<unsigned*>(&p2), *reinterpret_cast<unsigned*>(&p3));
    }
}

// ---------------- normalize / pad ----------------
__global__ void z0_norm(__nv_bfloat162* __restrict__ z, const float* __restrict__ den)
{
    size_t i = (size_t)blockIdx.x * 256 + threadIdx.x;
    const size_t tot = (size_t)R_NUM * N2T * 128;
    if (i >= tot) return;
    int c2 = i & 127;
    size_t row = i >> 7;
    int r = row / N2T; int n = (int)(row - (size_t)r * N2T);
    int h = c2 >> 5;
    float d = fmaxf(den[((size_t)n * R_NUM + r) * 4 + h], 1e-16f);
    float inv = __fdividef(1.f, d);
    __nv_bfloat162 v = z[i];
    z[i] = __floats2bfloat162_rn(__low2float(v) * inv, __high2float(v) * inv);
}

__global__ void z1_pad(const __nv_bfloat16* __restrict__ z, const float* __restrict__ den,
                       __nv_bfloat16* __restrict__ out)
{
    int i = blockIdx.x * 256 + threadIdx.x;
    const int tot = R_NUM * N2T * 64;
    if (i >= tot) return;
    int c = i & 63;
    int row = i >> 6;
    int r = row / N2T; int n = row - r * N2T;
    float v = 0.f;
    if (c < 40) {
        float inv = __fdividef(1.f, fmaxf(den[(size_t)n * R_NUM + r], 1e-16f));
        v = __bfloat162float(z[(size_t)row * 40 + c]) * inv;
    }
    out[i] = __float2bfloat16(v);
}

// ---------------- bilevel relation attention ----------------
__device__ __forceinline__ void relcoeff(const float psi[R_NUM][R_NUM],
                                         const float* wrel, float coeff[R_NUM])
{
#pragma unroll
    for (int s = 0; s < R_NUM; s++) coeff[s] = 0.f;
#pragma unroll
    for (int r = 0; r < R_NUM; r++) {
        float rsum = 0.f;
#pragma unroll
        for (int s = 0; s < R_NUM; s++) rsum += psi[r][s];
        float pv[R_NUM], mx = -INFINITY;
#pragma unroll
        for (int s = 0; s < R_NUM; s++) {
            float xx = psi[r][s];
            bool masked = (xx == 0.f) && (rsum != 0.f);
            pv[s] = masked ? -INFINITY : xx;
            mx = fmaxf(mx, pv[s]);
        }
        float pe[R_NUM], se = 0.f;
#pragma unroll
        for (int s = 0; s < R_NUM; s++) {
            float e = isinf(pv[s]) ? 0.f : expf(pv[s] - mx);
            pe[s] = e; se += e;
        }
        float inv = wrel[r] / se;
#pragma unroll
        for (int s = 0; s < R_NUM; s++) coeff[s] += pe[s] * inv;
    }
}

// layer0: warp per (n,h). q/k/v bf16 [R][N2T][256]; self from h0all; out bf16 + relu
__global__ void attn0_kernel(const __nv_bfloat16* __restrict__ q,
                             const __nv_bfloat16* __restrict__ k,
                             const __nv_bfloat16* __restrict__ v,
                             const float* __restrict__ wrel,
                             const float* __restrict__ hall,
                             __nv_bfloat16* __restrict__ outbf)
{
    int w = (blockIdx.x * blockDim.x + threadIdx.x) >> 5;
    int lane = threadIdx.x & 31;
    if (w >= N2T * 4) return;
    int n = w >> 2, h = w & 3;
    size_t base = (size_t)n * 256 + h * 64;
    const size_t rst = (size_t)N2T * 256;
    int c0 = lane, c1 = lane + 32;

    float qv[R_NUM][2], kv[R_NUM][2], vv[R_NUM][2];
#pragma unroll
    for (int r = 0; r < R_NUM; r++) {
        size_t o = (size_t)r * rst + base;
        qv[r][0] = __bfloat162float(q[o + c0]); qv[r][1] = __bfloat162float(q[o + c1]);
        kv[r][0] = __bfloat162float(k[o + c0]); kv[r][1] = __bfloat162float(k[o + c1]);
        vv[r][0] = __bfloat162float(v[o + c0]); vv[r][1] = __bfloat162float(v[o + c1]);
    }
    float psi[R_NUM][R_NUM];
#pragma unroll
    for (int r = 0; r < R_NUM; r++)
#pragma unroll
        for (int s = 0; s < R_NUM; s++) {
            float p = qv[r][0] * kv[s][0] + qv[r][1] * kv[s][1];
#pragma unroll
            for (int o = 16; o; o >>= 1) p += __shfl_xor_sync(0xffffffffu, p, o);
            psi[r][s] = p;
        }
    float coeff[R_NUM];
    relcoeff(psi, wrel, coeff);

    const float* self = hall + (size_t)n * 512 + 256 + h * 64;
#pragma unroll
    for (int jj = 0; jj < 2; jj++) {
        int c = lane + 32 * jj;
        float acc = 0.f;
#pragma unroll
        for (int s = 0; s < R_NUM; s++) acc += coeff[s] * vv[s][jj];
        float val = self[c] + acc;
        outbf[base + c] = __float2bfloat16(fmaxf(val, 0.f));
    }
}

// layer1: warp per node. qkv f32 [R][N2T][120]; fused log_softmax
__global__ void attn1_ls(const float* __restrict__ qkv, const float* __restrict__ wrel,
                         const float* __restrict__ hall, float* __restrict__ out)
{
    int w = (blockIdx.x * blockDim.x + threadIdx.x) >> 5;
    int lane = threadIdx.x & 31;
    if (w >= N2T) return;
    int n = w;
    const size_t rst = (size_t)N2T * 120;
    size_t base = (size_t)n * 120;
    bool ok1 = lane < 8;

    float qv[R_NUM][2], kv[R_NUM][2], vv[R_NUM][2];
#pragma unroll
    for (int r = 0; r < R_NUM; r++) {
        const float* p = qkv + (size_t)r * rst + base;
        qv[r][0] = p[lane];      qv[r][1] = ok1 ? p[32 + lane] : 0.f;
        kv[r][0] = p[40 + lane]; kv[r][1] = ok1 ? p[72 + lane] : 0.f;
        vv[r][0] = p[80 + lane]; vv[r][1] = ok1 ? p[112 + lane] : 0.f;
    }
    float psi[R_NUM][R_NUM];
#pragma unroll
    for (int r = 0; r < R_NUM; r++)
#pragma unroll
        for (int s = 0; s < R_NUM; s++) {
            float p = qv[r][0] * kv[s][0] + qv[r][1] * kv[s][1];
#pragma unroll
            for (int o = 16; o; o >>= 1) p += __shfl_xor_sync(0xffffffffu, p, o);
            psi[r][s] = p;
        }
    float coeff[R_NUM];
    relcoeff(psi, wrel, coeff);

    const float* self = hall + (size_t)n * 120 + 80;
    float a0 = 0.f, a1 = 0.f;
#pragma unroll
    for (int s = 0; s < R_NUM; s++) { a0 += coeff[s] * vv[s][0]; a1 += coeff[s] * vv[s][1]; }
    float v0 = self[lane] + a0;
    float v1 = ok1 ? (self[32 + lane] + a1) : -INFINITY;

    float mx = fmaxf(v0, v1);
#pragma unroll
    for (int o = 16; o; o >>= 1) mx = fmaxf(mx, __shfl_xor_sync(0xffffffffu, mx, o));
    float se = expf(v0 - mx) + (ok1 ? expf(v1 - mx) : 0.f);
#pragma unroll
    for (int o = 16; o; o >>= 1) se += __shfl_xor_sync(0xffffffffu, se, o);
    float lse = mx + logf(se);
    out[(size_t)n * 40 + lane] = v0 - lse;
    if (ok1) out[(size_t)n * 40 + 32 + lane] = v1 - lse;
}

// ---------------- host ----------------
extern "C" void kernel_launch(void* const* d_in, const int* in_sizes, int n_in,
                              void* d_out, int out_size)
{
    const int*   n_id  = (const int*)d_in[0];
    const int*   lni   = (const int*)d_in[1];
    const int*   ei0   = (const int*)d_in[3];
    const int*   et0   = (const int*)d_in[4];
    const int*   ei1   = (const int*)d_in[5];
    const int*   et1   = (const int*)d_in[6];
    const float* emb   = (const float*)d_in[7];
    const float* Wj0   = (const float*)d_in[8];
    const float* Wi0   = (const float*)d_in[9];
    const float* attj0 = (const float*)d_in[10];
    const float* atti0 = (const float*)d_in[11];
    const float* Wq0   = (const float*)d_in[12];
    const float* Wk0   = (const float*)d_in[13];
    const float* Wv0   = (const float*)d_in[14];
    const float* sw0   = (const float*)d_in[15];
    const float* sb0   = (const float*)d_in[16];
    const float* Wrel0 = (const float*)d_in[17];
    const float* Wj1   = (const float*)d_in[18];
    const float* Wi1   = (const float*)d_in[19];
    const float* attj1 = (const float*)d_in[20];
    const float* atti1 = (const float*)d_in[21];
    const float* Wq1   = (const float*)d_in[22];
    const float* Wk1   = (const float*)d_in[23];
    const float* Wv1   = (const float*)d_in[24];
    const float* sw1   = (const float*)d_in[25];
    const float* sb1   = (const float*)d_in[26];
    const float* Wrel1 = (const float*)d_in[27];

    int E0 = in_sizes[4];
    int E1 = in_sizes[6];

    __nv_bfloat16 *xbf, *z0bf, *qkv0bf, *x1bf, *z1bf, *z1p;
    __nv_bfloat16 *wj0t, *w0pack, *wqkv0t, *w1pack, *wqkv1t;
    float *hj0, *h0all, *den0, *h1all, *den1, *qkv1, *b0pack, *b1pack;
    cudaGetSymbolAddress((void**)&xbf,    g_xbf);
    cudaGetSymbolAddress((void**)&hj0,    g_hj0);
    cudaGetSymbolAddress((void**)&h0all,  g_h0all);
    cudaGetSymbolAddress((void**)&den0,   g_den0);
    cudaGetSymbolAddress((void**)&z0bf,   g_z0bf);
    cudaGetSymbolAddress((void**)&qkv0bf, g_qkv0bf);
    cudaGetSymbolAddress((void**)&x1bf,   g_x1bf);
    cudaGetSymbolAddress((void**)&h1all,  g_h1all);
    cudaGetSymbolAddress((void**)&den1,   g_den1);
    cudaGetSymbolAddress((void**)&z1bf,   g_z1bf);
    cudaGetSymbolAddress((void**)&z1p,    g_z1p);
    cudaGetSymbolAddress((void**)&qkv1,   g_qkv1);
    cudaGetSymbolAddress((void**)&wj0t,   g_wj0t);
    cudaGetSymbolAddress((void**)&w0pack, g_w0pack);
    cudaGetSymbolAddress((void**)&b0pack, g_b0pack);
    cudaGetSymbolAddress((void**)&wqkv0t, g_wqkv0t);
    cudaGetSymbolAddress((void**)&w1pack, g_w1pack);
    cudaGetSymbolAddress((void**)&b1pack, g_b1pack);
    cudaGetSymbolAddress((void**)&wqkv1t, g_wqkv1t);

    // ---- prep (weights + zero-fills) + gather ----
    mega_prep<<<B_TOT, 256>>>(Wj0, Wi0, sw0, sb0, Wq0, Wk0, Wv0,
                              Wj1, Wi1, sw1, sb1, Wq1, Wk1, Wv1,
                              wj0t, w0pack, b0pack, wqkv0t, w1pack, b1pack, wqkv1t,
                              (uint4*)den0, (uint4*)z0bf, (uint4*)den1, (uint4*)z1bf);
    gather_bf<<<cdiv(N1T * 32, 256), 256>>>(emb, n_id, lni, xbf);

    // ---- layer 0 ----
    gemm_tc_f32<<<dim3(2, cdiv(N1T, TBM)), 256>>>(xbf, wj0t, nullptr, hj0, N1T, 256, IN_DIM);
    gemm_tc_f32<<<dim3(4, cdiv(N2T, TBM)), 256>>>(xbf, w0pack, b0pack, h0all, N2T, 512, IN_DIM);

    edge_fused0<<<cdiv(E0 * 32, 256), 256>>>(ei0, ei0 + E0, et0, hj0, h0all,
                                             attj0, atti0, den0, z0bf, E0);
    z0_norm<<<cdiv(R_NUM * N2T * 128, 256), 256>>>((__nv_bfloat162*)z0bf, den0);

    gemm_tc_qkv0<<<dim3(2, cdiv(N2T, TBM), 15), 256>>>(
        z0bf, (size_t)N2T * HC0,
        wqkv0t, (size_t)HC0 * HC0,
        qkv0bf, (size_t)N2T * HC0,
        N2T, HC0, HC0);

    {
        const __nv_bfloat16* q0 = qkv0bf;
        const __nv_bfloat16* k0 = qkv0bf + (size_t)R_NUM * N2T * HC0;
        const __nv_bfloat16* v0 = qkv0bf + (size_t)2 * R_NUM * N2T * HC0;
        attn0_kernel<<<cdiv(N2T * 4 * 32, 256), 256>>>(q0, k0, v0, Wrel0, h0all, x1bf);
    }

    // ---- layer 1 ----
    gemm_tc_f32<<<dim3(1, cdiv(N2T, TBM)), 256>>>(x1bf, w1pack, b1pack, h1all, N2T, 120, HC0);

    edge_fused1<<<cdiv(E1 * 32, 256), 256>>>(ei1, ei1 + E1, et1, h1all,
                                             attj1, atti1, den1, z1bf, E1);
    z1_pad<<<cdiv(R_NUM * N2T * 64, 256), 256>>>(z1bf, den1, z1p);

    gemm_tc_batch_f32<<<dim3(1, cdiv(N2T, TBM), R_NUM), 256>>>(
        z1p, (size_t)N2T * 64,
        wqkv1t, (size_t)120 * 64,
        qkv1, (size_t)N2T * 120,
        N2T, 120, 64);

    attn1_ls<<<cdiv(N2T * 32, 256), 256>>>(qkv1, Wrel1, h1all, (float*)d_out);
}